// round 4
// baseline (speedup 1.0000x reference)
#include <cuda_runtime.h>
#include <math.h>
#include <stdint.h>

// Problem constants
#define PB  2      // batch
#define PS  2048   // sequence
#define PH  8      // heads
#define PDH 64     // head dim
#define PDM 512    // model dim
#define NBH (PB*PH)

// ---------------- scratch (static device globals; no allocations) ----------
__device__ float g_q[(size_t)NBH * PS * PDH];     // [b,h,s,d]  8 MB
__device__ float g_k[(size_t)NBH * PS * PDH];
__device__ float g_v[(size_t)NBH * PS * PDH];
__device__ float g_p[(size_t)NBH * PS * PDH];
__device__ float g_score[(size_t)NBH * PS * PS];  // [b,h,i,j]  256 MB
__device__ float g_ctx[(size_t)PB * PS * PDM];    // [b,s,h*d]  8 MB

// ---------------------------------------------------------------------------
// Projection GEMM: C[M,512] = A[M,512] @ W[512,512] (+ bias)
// mode 0: out[m*512 + n]
// mode 1: out[((b*H+h)*S + s)*64 + d]   (m = b*S+s, n = h*64+d)
// Block: 256 threads, 64x64 tile, BK=32, 4x4 microtile.
// ---------------------------------------------------------------------------
__global__ void proj_kernel(const float* __restrict__ A,
                            const float* __restrict__ W,
                            const float* __restrict__ bias,
                            float* __restrict__ out, int mode)
{
    const int BM = 64, BN = 64, BK = 32;
    __shared__ float As[BK][BM + 1];
    __shared__ float Ws[BK][BN + 1];

    const int bm  = blockIdx.y * BM;
    const int bn  = blockIdx.x * BN;
    const int tid = threadIdx.x;
    const int tx  = tid & 15;
    const int ty  = tid >> 4;

    float acc[4][4] = {};

    for (int kt = 0; kt < PDM; kt += BK) {
        #pragma unroll
        for (int idx = tid; idx < BM * BK; idx += 256) {
            int m = idx / BK, k = idx % BK;
            As[k][m] = A[(size_t)(bm + m) * PDM + kt + k];
        }
        #pragma unroll
        for (int idx = tid; idx < BK * BN; idx += 256) {
            int k = idx / BN, n = idx % BN;
            Ws[k][n] = W[(size_t)(kt + k) * PDM + bn + n];
        }
        __syncthreads();
        #pragma unroll
        for (int k = 0; k < BK; k++) {
            float a[4], b[4];
            #pragma unroll
            for (int i = 0; i < 4; i++) a[i] = As[k][ty * 4 + i];
            #pragma unroll
            for (int j = 0; j < 4; j++) b[j] = Ws[k][tx * 4 + j];
            #pragma unroll
            for (int i = 0; i < 4; i++)
                #pragma unroll
                for (int j = 0; j < 4; j++)
                    acc[i][j] = fmaf(a[i], b[j], acc[i][j]);
        }
        __syncthreads();
    }

    #pragma unroll
    for (int i = 0; i < 4; i++) {
        int m = bm + ty * 4 + i;
        #pragma unroll
        for (int j = 0; j < 4; j++) {
            int n = bn + tx * 4 + j;
            float v = acc[i][j] + (bias ? bias[n] : 0.0f);
            if (mode == 0) {
                out[(size_t)m * PDM + n] = v;
            } else {
                int b_ = m / PS, s_ = m % PS;
                int h_ = n / PDH, d_ = n % PDH;
                out[(((size_t)(b_ * PH + h_) * PS + s_)) * PDH + d_] = v;
            }
        }
    }
}

// ---------------------------------------------------------------------------
// Score GEMM: per (b,h):  T[i,j] = sum_d (Q[i,d] + hb[h,d]) * M[j,d]
// scatter == 0 : score[bh][i][j]  = T[i,j]           (content pass)
// scatter == 1 : rel-shift fused scatter-add into score (pos pass)
//   posraw (i,c) maps to:
//     c >= S-1-i            -> score[i][c - (S-1) + i]     += val
//     else (i >= 1)         -> score[i-1][c + i + 1]       += val
//     (i==0, c<S-1)         -> dropped;  col j'=i'+1 stays untouched (== +0)
//   Map is injective -> plain += is race-free (content pass already done).
// Block: 256 threads, 64x64 tile, full K=64 in smem, 4x4 microtile.
// ---------------------------------------------------------------------------
__global__ void score_kernel(const float* __restrict__ Q,
                             const float* __restrict__ M,
                             const float* __restrict__ hb,
                             float* __restrict__ score, int scatter)
{
    const int BT = 64;
    __shared__ float Qs[PDH][BT + 1];
    __shared__ float Ms[PDH][BT + 1];

    const int bh = blockIdx.z;
    const int h  = bh % PH;
    const int i0 = blockIdx.y * BT;
    const int j0 = blockIdx.x * BT;

    const float* Qb = Q + (size_t)bh * PS * PDH;
    const float* Mb = M + (size_t)bh * PS * PDH;
    const int tid = threadIdx.x;

    #pragma unroll
    for (int idx = tid; idx < BT * PDH; idx += 256) {
        int m = idx / PDH, d = idx % PDH;
        Qs[d][m] = Qb[(size_t)(i0 + m) * PDH + d] + hb[h * PDH + d];
        Ms[d][m] = Mb[(size_t)(j0 + m) * PDH + d];
    }
    __syncthreads();

    const int tx = tid & 15;
    const int ty = tid >> 4;
    float acc[4][4] = {};

    #pragma unroll
    for (int d = 0; d < PDH; d++) {
        float a[4], b[4];
        #pragma unroll
        for (int i = 0; i < 4; i++) a[i] = Qs[d][ty * 4 + i];
        #pragma unroll
        for (int j = 0; j < 4; j++) b[j] = Ms[d][tx * 4 + j];
        #pragma unroll
        for (int i = 0; i < 4; i++)
            #pragma unroll
            for (int j = 0; j < 4; j++)
                acc[i][j] = fmaf(a[i], b[j], acc[i][j]);
    }

    float* sb = score + (size_t)bh * PS * PS;

    if (scatter == 0) {
        #pragma unroll
        for (int i = 0; i < 4; i++) {
            int gi = i0 + ty * 4 + i;
            #pragma unroll
            for (int j = 0; j < 4; j++) {
                int gj = j0 + tx * 4 + j;
                sb[(size_t)gi * PS + gj] = acc[i][j];
            }
        }
    } else {
        #pragma unroll
        for (int i = 0; i < 4; i++) {
            int gi = i0 + ty * 4 + i;
            #pragma unroll
            for (int j = 0; j < 4; j++) {
                int c = j0 + tx * 4 + j;
                float v = acc[i][j];
                if (c >= PS - 1 - gi) {
                    int jj = c - (PS - 1) + gi;
                    sb[(size_t)gi * PS + jj] += v;
                } else if (gi >= 1) {
                    sb[(size_t)(gi - 1) * PS + (c + gi + 1)] += v;
                }
            }
        }
    }
}

// ---------------------------------------------------------------------------
// Row softmax, in place. One block (256 threads) per row of score.
// x = score/sqrt(512); masked cols -> -1e9; softmax over j.
// ---------------------------------------------------------------------------
__global__ void softmax_kernel(float* __restrict__ score,
                               const unsigned char* __restrict__ mask)
{
    const size_t row = blockIdx.x;          // bh*S + i
    const int bh = (int)(row / PS);
    const int b_ = bh / PH;
    float* p = score + row * (size_t)PS;
    const unsigned char* mrow = mask + (size_t)b_ * PS;

    const int tid = threadIdx.x;
    const float scale = 0.044194173824159216f;  // 1/sqrt(512)

    __shared__ float red[256];

    float vals[8];
    float mx = -INFINITY;
    #pragma unroll
    for (int t = 0; t < 8; t++) {
        int j = tid + t * 256;
        float x = p[j] * scale;
        if (mrow[j]) x = -1e9f;
        vals[t] = x;
        mx = fmaxf(mx, x);
    }
    red[tid] = mx;
    __syncthreads();
    for (int s = 128; s > 0; s >>= 1) {
        if (tid < s) red[tid] = fmaxf(red[tid], red[tid + s]);
        __syncthreads();
    }
    mx = red[0];
    __syncthreads();

    float sum = 0.0f;
    #pragma unroll
    for (int t = 0; t < 8; t++) {
        vals[t] = expf(vals[t] - mx);
        sum += vals[t];
    }
    red[tid] = sum;
    __syncthreads();
    for (int s = 128; s > 0; s >>= 1) {
        if (tid < s) red[tid] += red[tid + s];
        __syncthreads();
    }
    float inv = 1.0f / red[0];

    #pragma unroll
    for (int t = 0; t < 8; t++)
        p[tid + t * 256] = vals[t] * inv;
}

// ---------------------------------------------------------------------------
// attn @ V : per (b,h):  ctx[b, i, h*64+d] = sum_j attn[i,j] * V[j,d]
// Block: 256 threads, 64 rows x 64 cols (full Dh), BK=64, 4x4 microtile.
// ---------------------------------------------------------------------------
__global__ void av_kernel(const float* __restrict__ attn,
                          const float* __restrict__ V,
                          float* __restrict__ ctx)
{
    const int BM = 64, BK = 64;
    __shared__ float Ps[BK][BM + 1];   // attn tile, k-major
    __shared__ float Vs[BK][PDH + 1];  // V tile

    const int bh = blockIdx.z;
    const int b_ = bh / PH;
    const int h  = bh % PH;
    const int i0 = blockIdx.y * BM;
    const int tid = threadIdx.x;
    const int tx = tid & 15;
    const int ty = tid >> 4;

    const float* Ab = attn + (size_t)bh * PS * PS;
    const float* Vb = V + (size_t)bh * PS * PDH;

    float acc[4][4] = {};

    for (int kt = 0; kt < PS; kt += BK) {
        #pragma unroll
        for (int idx = tid; idx < BM * BK; idx += 256) {
            int m = idx / BK, k = idx % BK;
            Ps[k][m] = Ab[(size_t)(i0 + m) * PS + kt + k];
        }
        #pragma unroll
        for (int idx = tid; idx < BK * PDH; idx += 256) {
            int k = idx / PDH, n = idx % PDH;
            Vs[k][n] = Vb[(size_t)(kt + k) * PDH + n];
        }
        __syncthreads();
        #pragma unroll
        for (int k = 0; k < BK; k++) {
            float a[4], b[4];
            #pragma unroll
            for (int i = 0; i < 4; i++) a[i] = Ps[k][ty * 4 + i];
            #pragma unroll
            for (int j = 0; j < 4; j++) b[j] = Vs[k][tx * 4 + j];
            #pragma unroll
            for (int i = 0; i < 4; i++)
                #pragma unroll
                for (int j = 0; j < 4; j++)
                    acc[i][j] = fmaf(a[i], b[j], acc[i][j]);
        }
        __syncthreads();
    }

    #pragma unroll
    for (int i = 0; i < 4; i++) {
        int s_ = i0 + ty * 4 + i;
        #pragma unroll
        for (int j = 0; j < 4; j++) {
            int d_ = tx * 4 + j;
            ctx[((size_t)b_ * PS + s_) * PDM + h * PDH + d_] = acc[i][j];
        }
    }
}

// ---------------------------------------------------------------------------
extern "C" void kernel_launch(void* const* d_in, const int* in_sizes, int n_in,
                              void* d_out, int out_size)
{
    const float* query = (const float*)d_in[0];
    const float* key   = (const float*)d_in[1];
    const float* value = (const float*)d_in[2];
    const float* pos   = (const float*)d_in[3];
    const unsigned char* mask = (const unsigned char*)d_in[4];
    const float* Wq = (const float*)d_in[5];
    const float* bq = (const float*)d_in[6];
    const float* Wk = (const float*)d_in[7];
    const float* bk = (const float*)d_in[8];
    const float* Wv = (const float*)d_in[9];
    const float* bv = (const float*)d_in[10];
    const float* Wp = (const float*)d_in[11];
    const float* Wo = (const float*)d_in[12];
    const float* bo = (const float*)d_in[13];
    const float* ub = (const float*)d_in[14];
    const float* vb = (const float*)d_in[15];

    float *q, *k, *v, *p, *score, *ctx;
    cudaGetSymbolAddress((void**)&q, g_q);
    cudaGetSymbolAddress((void**)&k, g_k);
    cudaGetSymbolAddress((void**)&v, g_v);
    cudaGetSymbolAddress((void**)&p, g_p);
    cudaGetSymbolAddress((void**)&score, g_score);
    cudaGetSymbolAddress((void**)&ctx, g_ctx);

    dim3 tb(256);

    // 1) projections -> [b,h,s,d]
    dim3 gproj(PDM / 64, (PB * PS) / 64);
    proj_kernel<<<gproj, tb>>>(query, Wq, bq, q, 1);
    proj_kernel<<<gproj, tb>>>(key,   Wk, bk, k, 1);
    proj_kernel<<<gproj, tb>>>(value, Wv, bv, v, 1);
    proj_kernel<<<gproj, tb>>>(pos,   Wp, nullptr, p, 1);

    // 2) content scores, then pos scores with fused rel-shift scatter-add
    dim3 gscore(PS / 64, PS / 64, NBH);
    score_kernel<<<gscore, tb>>>(q, k, ub, score, 0);
    score_kernel<<<gscore, tb>>>(q, p, vb, score, 1);

    // 3) softmax (in place)
    softmax_kernel<<<NBH * PS, tb>>>(score, mask);

    // 4) attn @ V -> ctx [b,s,h*d]
    av_kernel<<<dim3(1, PS / 64, NBH), tb>>>(score, v, ctx);

    // 5) output projection -> d_out [b,s,512]
    proj_kernel<<<gproj, tb>>>(ctx, Wo, bo, (float*)d_out, 0);
}

// round 6
// speedup vs baseline: 1.5357x; 1.5357x over previous
#include <cuda_runtime.h>
#include <cuda_bf16.h>
#include <math.h>
#include <stdint.h>

// Problem constants
#define PB  2      // batch
#define PS  2048   // sequence
#define PH  8      // heads
#define PDH 64     // head dim
#define PDM 512    // model dim
#define NBH (PB*PH)

// ---------------- scratch (static device globals; no allocations) ----------
__device__ float g_q[(size_t)NBH * PS * PDH];     // [b,h,s,d]  8 MB
__device__ float g_k[(size_t)NBH * PS * PDH];
__device__ float g_v[(size_t)NBH * PS * PDH];
__device__ float g_p[(size_t)NBH * PS * PDH];
__device__ float g_score[(size_t)NBH * PS * PS];  // [b,h,i,j]  256 MB
__device__ float g_ctx[(size_t)PB * PS * PDM];    // [b,s,h*d]  8 MB

// =========================== helpers =======================================
__device__ __forceinline__ uint32_t smem_u32(const void* p) {
    uint32_t a;
    asm("{ .reg .u64 t; cvta.to.shared.u64 t, %1; cvt.u32.u64 %0, t; }"
        : "=r"(a) : "l"(p));
    return a;
}

// ---------------------------------------------------------------------------
// Projection GEMM: C[M,512] = A[M,512] @ W[512,512] (+ bias)
// mode 0: out[m*512 + n]
// mode 1: out[((b*H+h)*S + s)*64 + d]   (m = b*S+s, n = h*64+d; BN=64 aligned
//         with head width so each block serves exactly one head)
// Block: 256 threads, 128x64 tile, BK=32, 8x4 microtile, float4 everywhere.
// ---------------------------------------------------------------------------
__global__ __launch_bounds__(256) void proj_kernel(const float* __restrict__ A,
                                                   const float* __restrict__ W,
                                                   const float* __restrict__ bias,
                                                   float* __restrict__ out, int mode)
{
    const int BM = 128, BN = 64, BK = 32;
    __shared__ __align__(16) float As[BK][BM + 4];
    __shared__ __align__(16) float Ws[BK][BN + 4];

    const int bm  = blockIdx.y * BM;
    const int bn  = blockIdx.x * BN;
    const int tid = threadIdx.x;
    const int tx  = tid & 15;      // 16 -> 4 cols each
    const int ty  = tid >> 4;      // 16 -> 8 rows each

    float acc[8][4] = {};

    for (int kt = 0; kt < PDM; kt += BK) {
        #pragma unroll
        for (int idx = tid; idx < 1024; idx += 256) {       // 128x32 / 4
            int m = idx >> 3, kq = (idx & 7) * 4;
            float4 a = *(const float4*)&A[(size_t)(bm + m) * PDM + kt + kq];
            As[kq + 0][m] = a.x; As[kq + 1][m] = a.y;
            As[kq + 2][m] = a.z; As[kq + 3][m] = a.w;
        }
        #pragma unroll
        for (int idx = tid; idx < 512; idx += 256) {        // 32x64 / 4
            int k = idx >> 4, nq = (idx & 15) * 4;
            *(float4*)&Ws[k][nq] = *(const float4*)&W[(size_t)(kt + k) * PDM + bn + nq];
        }
        __syncthreads();
        #pragma unroll
        for (int k = 0; k < BK; k++) {
            float a[8], b[4];
            *(float4*)&a[0] = *(float4*)&As[k][ty * 8];
            *(float4*)&a[4] = *(float4*)&As[k][ty * 8 + 4];
            *(float4*)&b[0] = *(float4*)&Ws[k][tx * 4];
            #pragma unroll
            for (int i = 0; i < 8; i++)
                #pragma unroll
                for (int j = 0; j < 4; j++)
                    acc[i][j] = fmaf(a[i], b[j], acc[i][j]);
        }
        __syncthreads();
    }

    float bb[4] = {0.f, 0.f, 0.f, 0.f};
    if (bias) *(float4*)&bb[0] = *(const float4*)&bias[bn + tx * 4];

    #pragma unroll
    for (int i = 0; i < 8; i++) {
        int m = bm + ty * 8 + i;
        float4 v = make_float4(acc[i][0] + bb[0], acc[i][1] + bb[1],
                               acc[i][2] + bb[2], acc[i][3] + bb[3]);
        if (mode == 0) {
            *(float4*)&out[(size_t)m * PDM + bn + tx * 4] = v;
        } else {
            int b_ = m / PS, s_ = m % PS;
            int h_ = bn / PDH;            // whole block = one head (BN==PDH)
            *(float4*)&out[(((size_t)(b_ * PH + h_) * PS + s_)) * PDH + tx * 4] = v;
        }
    }
}

// ---------------------------------------------------------------------------
// Tensor-core score GEMM (mma.sync bf16, HMMA): per (b,h)
//   T[i,j] = sum_d (Q[i,d] + hb[h,d]) * M[j,d]       (128x128 tile / block)
// scatter == 0 : score[bh][i][j]  = T[i,j]           (content pass)
// scatter == 1 : rel-shift fused scatter-add (pos pass), map (proven R1-R4):
//     c >= S-1-i  -> score[i][c-(S-1)+i]   += val
//     else, i>=1  -> score[i-1][c+i+1]     += val
//     (i==0, c<S-1 dropped; col j'=i'+1 untouched == +0). Injective -> no races.
//
// 8 warps in 2(M) x 4(N): each warp 64x32 = 4x4 m16n8k16 atoms, 4 K-steps.
// A fragments via ldmatrix.x4 (row-major, K contig); B fragments via
// ldmatrix.x2 on [n][k] K-contiguous layout (matches col-major B fragment).
// ---------------------------------------------------------------------------
__global__ __launch_bounds__(256) void score_mma_kernel(const float* __restrict__ Q,
                                                        const float* __restrict__ M,
                                                        const float* __restrict__ hb,
                                                        float* __restrict__ score,
                                                        int scatter)
{
    const int LDS = 72;  // bf16 stride (64 + 8 pad) -> 144B rows, conflict-free ldmatrix
    __shared__ __align__(16) __nv_bfloat16 As[128 * LDS];
    __shared__ __align__(16) __nv_bfloat16 Bs[128 * LDS];

    const int tid  = threadIdx.x;
    const int wid  = tid >> 5;
    const int lane = tid & 31;
    const int bh = blockIdx.z;
    const int h  = bh & (PH - 1);
    const int i0 = blockIdx.y * 128;
    const int j0 = blockIdx.x * 128;

    // Stage fp32 -> bf16 (pairwise packs, 4B stores, conflict-free).
    const float* Qb = Q + (size_t)bh * PS * PDH;
    const float* Mb = M + (size_t)bh * PS * PDH;
    #pragma unroll
    for (int idx = tid; idx < 128 * 32; idx += 256) {
        int r = idx >> 5, pc = idx & 31;
        float2 q2 = *(const float2*)&Qb[(size_t)(i0 + r) * PDH + 2 * pc];
        float2 b2 = *(const float2*)&hb[h * PDH + 2 * pc];
        __nv_bfloat162 pk = __floats2bfloat162_rn(q2.x + b2.x, q2.y + b2.y);
        *(uint32_t*)&As[r * LDS + pc * 2] = *(uint32_t*)&pk;
    }
    #pragma unroll
    for (int idx = tid; idx < 128 * 32; idx += 256) {
        int r = idx >> 5, pc = idx & 31;
        float2 m2 = *(const float2*)&Mb[(size_t)(j0 + r) * PDH + 2 * pc];
        __nv_bfloat162 pk = __floats2bfloat162_rn(m2.x, m2.y);
        *(uint32_t*)&Bs[r * LDS + pc * 2] = *(uint32_t*)&pk;
    }
    __syncthreads();

    const int wm = wid >> 2;       // 0..1 : 64 rows
    const int wn = wid & 3;        // 0..3 : 32 cols
    const uint32_t a_base = smem_u32(As);
    const uint32_t b_base = smem_u32(Bs);

    float acc[4][4][4] = {};

    #pragma unroll
    for (int ks = 0; ks < 4; ks++) {
        const int k0 = ks * 16;
        uint32_t a[4][4];
        #pragma unroll
        for (int mt = 0; mt < 4; mt++) {
            int row = wm * 64 + mt * 16 + (lane & 15);
            int col = k0 + ((lane >> 4) << 3);
            uint32_t addr = a_base + (uint32_t)(row * LDS + col) * 2;
            asm volatile("ldmatrix.sync.aligned.m8n8.x4.shared.b16 {%0,%1,%2,%3}, [%4];"
                         : "=r"(a[mt][0]), "=r"(a[mt][1]), "=r"(a[mt][2]), "=r"(a[mt][3])
                         : "r"(addr));
        }
        uint32_t b[4][2];
        #pragma unroll
        for (int nt = 0; nt < 4; nt++) {
            int l16 = lane & 15;
            int row = wn * 32 + nt * 8 + (l16 & 7);
            int col = k0 + ((l16 >> 3) << 3);
            uint32_t addr = b_base + (uint32_t)(row * LDS + col) * 2;
            asm volatile("ldmatrix.sync.aligned.m8n8.x2.shared.b16 {%0,%1}, [%2];"
                         : "=r"(b[nt][0]), "=r"(b[nt][1])
                         : "r"(addr));
        }
        #pragma unroll
        for (int mt = 0; mt < 4; mt++)
            #pragma unroll
            for (int nt = 0; nt < 4; nt++)
                asm volatile(
                    "mma.sync.aligned.m16n8k16.row.col.f32.bf16.bf16.f32 "
                    "{%0,%1,%2,%3}, {%4,%5,%6,%7}, {%8,%9}, {%0,%1,%2,%3};"
                    : "+f"(acc[mt][nt][0]), "+f"(acc[mt][nt][1]),
                      "+f"(acc[mt][nt][2]), "+f"(acc[mt][nt][3])
                    : "r"(a[mt][0]), "r"(a[mt][1]), "r"(a[mt][2]), "r"(a[mt][3]),
                      "r"(b[nt][0]), "r"(b[nt][1]));
    }

    // Epilogue. Fragment layout: g = lane/4 (row), tg = lane%4 (col pair).
    // d0=(g, 2tg), d1=(g, 2tg+1), d2=(g+8, 2tg), d3=(g+8, 2tg+1).
    const int g  = lane >> 2;
    const int tg = lane & 3;
    float* sb = score + (size_t)bh * PS * PS;

    if (scatter == 0) {
        #pragma unroll
        for (int mt = 0; mt < 4; mt++) {
            int gi = i0 + wm * 64 + mt * 16 + g;
            #pragma unroll
            for (int nt = 0; nt < 4; nt++) {
                int gj = j0 + wn * 32 + nt * 8 + tg * 2;
                *(float2*)&sb[(size_t)gi * PS + gj] =
                    make_float2(acc[mt][nt][0], acc[mt][nt][1]);
                *(float2*)&sb[(size_t)(gi + 8) * PS + gj] =
                    make_float2(acc[mt][nt][2], acc[mt][nt][3]);
            }
        }
    } else {
        #pragma unroll
        for (int mt = 0; mt < 4; mt++) {
            #pragma unroll
            for (int nt = 0; nt < 4; nt++) {
                #pragma unroll
                for (int e = 0; e < 4; e++) {
                    int gi = i0 + wm * 64 + mt * 16 + g + (e >> 1) * 8;
                    int cg = j0 + wn * 32 + nt * 8 + tg * 2 + (e & 1);
                    float v = acc[mt][nt][e];
                    if (cg >= PS - 1 - gi) {
                        sb[(size_t)gi * PS + (cg - (PS - 1) + gi)] += v;
                    } else if (gi >= 1) {
                        sb[(size_t)(gi - 1) * PS + (cg + gi + 1)] += v;
                    }
                }
            }
        }
    }
}

// ---------------------------------------------------------------------------
// Row softmax, in place. One block (256 threads) per row; float4 + shuffles.
// ---------------------------------------------------------------------------
__global__ __launch_bounds__(256) void softmax_kernel(float* __restrict__ score,
                                                      const unsigned char* __restrict__ mask)
{
    const size_t row = blockIdx.x;           // bh*S + i
    const int bh = (int)(row / PS);
    const int b_ = bh / PH;
    float* p = score + row * (size_t)PS;
    const unsigned char* mrow = mask + (size_t)b_ * PS;

    const int tid  = threadIdx.x;
    const int lane = tid & 31;
    const int wid  = tid >> 5;
    const float scale = 0.044194173824159216f;   // 1/sqrt(512)

    __shared__ float s1[8];
    __shared__ float s2[8];

    float x[8];
    float4 v0 = *(const float4*)&p[8 * tid];
    float4 v1 = *(const float4*)&p[8 * tid + 4];
    x[0] = v0.x; x[1] = v0.y; x[2] = v0.z; x[3] = v0.w;
    x[4] = v1.x; x[5] = v1.y; x[6] = v1.z; x[7] = v1.w;
    unsigned long long mk = *(const unsigned long long*)&mrow[8 * tid];

    float mx = -INFINITY;
    #pragma unroll
    for (int t = 0; t < 8; t++) {
        x[t] = ((mk >> (8 * t)) & 0xffULL) ? -1e9f : x[t] * scale;
        mx = fmaxf(mx, x[t]);
    }
    #pragma unroll
    for (int o = 16; o > 0; o >>= 1)
        mx = fmaxf(mx, __shfl_xor_sync(0xffffffffu, mx, o));
    if (lane == 0) s1[wid] = mx;
    __syncthreads();
    mx = s1[0];
    #pragma unroll
    for (int w = 1; w < 8; w++) mx = fmaxf(mx, s1[w]);

    float sum = 0.0f;
    #pragma unroll
    for (int t = 0; t < 8; t++) {
        x[t] = expf(x[t] - mx);
        sum += x[t];
    }
    #pragma unroll
    for (int o = 16; o > 0; o >>= 1)
        sum += __shfl_xor_sync(0xffffffffu, sum, o);
    if (lane == 0) s2[wid] = sum;
    __syncthreads();
    sum = s2[0];
    #pragma unroll
    for (int w = 1; w < 8; w++) sum += s2[w];
    float inv = 1.0f / sum;

    v0 = make_float4(x[0] * inv, x[1] * inv, x[2] * inv, x[3] * inv);
    v1 = make_float4(x[4] * inv, x[5] * inv, x[6] * inv, x[7] * inv);
    *(float4*)&p[8 * tid]     = v0;
    *(float4*)&p[8 * tid + 4] = v1;
}

// ---------------------------------------------------------------------------
// attn @ V : per (b,h):  ctx[b, i, h*64+d] = sum_j attn[i,j] * V[j,d]
// Block: 256 threads, 128x64 tile, BK=32, 8x4 microtile, float4.
// ---------------------------------------------------------------------------
__global__ __launch_bounds__(256) void av_kernel(const float* __restrict__ attn,
                                                 const float* __restrict__ V,
                                                 float* __restrict__ ctx)
{
    const int BM = 128, BK = 32;
    __shared__ __align__(16) float Ps[BK][BM + 4];
    __shared__ __align__(16) float Vs[BK][PDH + 4];

    const int bh = blockIdx.z;
    const int b_ = bh / PH;
    const int h  = bh % PH;
    const int i0 = blockIdx.y * BM;
    const int tid = threadIdx.x;
    const int tx  = tid & 15;
    const int ty  = tid >> 4;

    const float* Ab = attn + (size_t)bh * PS * PS;
    const float* Vb = V + (size_t)bh * PS * PDH;

    float acc[8][4] = {};

    for (int kt = 0; kt < PS; kt += BK) {
        #pragma unroll
        for (int idx = tid; idx < 1024; idx += 256) {       // 128x32 / 4
            int m = idx >> 3, kq = (idx & 7) * 4;
            float4 a = *(const float4*)&Ab[(size_t)(i0 + m) * PS + kt + kq];
            Ps[kq + 0][m] = a.x; Ps[kq + 1][m] = a.y;
            Ps[kq + 2][m] = a.z; Ps[kq + 3][m] = a.w;
        }
        #pragma unroll
        for (int idx = tid; idx < 512; idx += 256) {        // 32x64 / 4
            int k = idx >> 4, nq = (idx & 15) * 4;
            *(float4*)&Vs[k][nq] = *(const float4*)&Vb[(size_t)(kt + k) * PDH + nq];
        }
        __syncthreads();
        #pragma unroll
        for (int k = 0; k < BK; k++) {
            float a[8], b[4];
            *(float4*)&a[0] = *(float4*)&Ps[k][ty * 8];
            *(float4*)&a[4] = *(float4*)&Ps[k][ty * 8 + 4];
            *(float4*)&b[0] = *(float4*)&Vs[k][tx * 4];
            #pragma unroll
            for (int i = 0; i < 8; i++)
                #pragma unroll
                for (int j = 0; j < 4; j++)
                    acc[i][j] = fmaf(a[i], b[j], acc[i][j]);
        }
        __syncthreads();
    }

    #pragma unroll
    for (int i = 0; i < 8; i++) {
        int s_ = i0 + ty * 8 + i;
        float4 v = make_float4(acc[i][0], acc[i][1], acc[i][2], acc[i][3]);
        *(float4*)&ctx[((size_t)b_ * PS + s_) * PDM + h * PDH + tx * 4] = v;
    }
}

// ---------------------------------------------------------------------------
extern "C" void kernel_launch(void* const* d_in, const int* in_sizes, int n_in,
                              void* d_out, int out_size)
{
    const float* query = (const float*)d_in[0];
    const float* key   = (const float*)d_in[1];
    const float* value = (const float*)d_in[2];
    const float* pos   = (const float*)d_in[3];
    const unsigned char* mask = (const unsigned char*)d_in[4];
    const float* Wq = (const float*)d_in[5];
    const float* bq = (const float*)d_in[6];
    const float* Wk = (const float*)d_in[7];
    const float* bk = (const float*)d_in[8];
    const float* Wv = (const float*)d_in[9];
    const float* bv = (const float*)d_in[10];
    const float* Wp = (const float*)d_in[11];
    const float* Wo = (const float*)d_in[12];
    const float* bo = (const float*)d_in[13];
    const float* ub = (const float*)d_in[14];
    const float* vb = (const float*)d_in[15];

    float *q, *k, *v, *p, *score, *ctx;
    cudaGetSymbolAddress((void**)&q, g_q);
    cudaGetSymbolAddress((void**)&k, g_k);
    cudaGetSymbolAddress((void**)&v, g_v);
    cudaGetSymbolAddress((void**)&p, g_p);
    cudaGetSymbolAddress((void**)&score, g_score);
    cudaGetSymbolAddress((void**)&ctx, g_ctx);

    dim3 tb(256);

    // 1) projections -> [b,h,s,d]
    dim3 gproj(PDM / 64, (PB * PS) / 128);
    proj_kernel<<<gproj, tb>>>(query, Wq, bq, q, 1);
    proj_kernel<<<gproj, tb>>>(key,   Wk, bk, k, 1);
    proj_kernel<<<gproj, tb>>>(value, Wv, bv, v, 1);
    proj_kernel<<<gproj, tb>>>(pos,   Wp, nullptr, p, 1);

    // 2) content scores (HMMA), then pos scores with fused rel-shift add
    dim3 gscore(PS / 128, PS / 128, NBH);
    score_mma_kernel<<<gscore, tb>>>(q, k, ub, score, 0);
    score_mma_kernel<<<gscore, tb>>>(q, p, vb, score, 1);

    // 3) softmax (in place)
    softmax_kernel<<<NBH * PS, tb>>>(score, mask);

    // 4) attn @ V -> ctx [b,s,h*d]
    av_kernel<<<dim3(1, PS / 128, NBH), tb>>>(score, v, ctx);

    // 5) output projection -> d_out [b,s,512]
    proj_kernel<<<gproj, tb>>>(ctx, Wo, bo, (float*)d_out, 0);
}

// round 7
// speedup vs baseline: 2.8187x; 1.8354x over previous
#include <cuda_runtime.h>
#include <cuda_bf16.h>
#include <math.h>
#include <stdint.h>

// Problem constants
#define PB  2      // batch
#define PS  2048   // sequence
#define PH  8      // heads
#define PDH 64     // head dim
#define PDM 512    // model dim
#define NBH (PB*PH)

#define SCALE 0.044194173824159216f   // 1/sqrt(512)

// ---------------- scratch (static device globals; no allocations) ----------
__device__ float g_q[(size_t)NBH * PS * PDH];     // [b,h,s,d]  8 MB
__device__ float g_k[(size_t)NBH * PS * PDH];
__device__ float g_v[(size_t)NBH * PS * PDH];
__device__ float g_p[(size_t)NBH * PS * PDH];
__device__ float g_score[(size_t)NBH * PS * PS];  // content scores / attn  256 MB
__device__ float g_pos[(size_t)NBH * PS * PS];    // UNSHIFTED pos scores   256 MB
__device__ float g_ctx[(size_t)PB * PS * PDM];    // [b,s,h*d]  8 MB

// =========================== helpers =======================================
__device__ __forceinline__ uint32_t smem_u32(const void* p) {
    uint32_t a;
    asm("{ .reg .u64 t; cvta.to.shared.u64 t, %1; cvt.u32.u64 %0, t; }"
        : "=r"(a) : "l"(p));
    return a;
}

#define LDSMX4(r, addr) \
    asm volatile("ldmatrix.sync.aligned.m8n8.x4.shared.b16 {%0,%1,%2,%3}, [%4];" \
                 : "=r"((r)[0]), "=r"((r)[1]), "=r"((r)[2]), "=r"((r)[3]) : "r"(addr))

#define LDSMX2(r, addr) \
    asm volatile("ldmatrix.sync.aligned.m8n8.x2.shared.b16 {%0,%1}, [%2];" \
                 : "=r"((r)[0]), "=r"((r)[1]) : "r"(addr))

#define MMA16816(d, a, b) \
    asm volatile("mma.sync.aligned.m16n8k16.row.col.f32.bf16.bf16.f32 " \
                 "{%0,%1,%2,%3}, {%4,%5,%6,%7}, {%8,%9}, {%0,%1,%2,%3};" \
                 : "+f"((d)[0]), "+f"((d)[1]), "+f"((d)[2]), "+f"((d)[3]) \
                 : "r"((a)[0]), "r"((a)[1]), "r"((a)[2]), "r"((a)[3]), \
                   "r"((b)[0]), "r"((b)[1]))

__device__ __forceinline__ void split2(float x0, float x1,
                                       uint32_t& hi, uint32_t& lo) {
    __nv_bfloat16 h0 = __float2bfloat16(x0);
    __nv_bfloat16 h1 = __float2bfloat16(x1);
    __nv_bfloat16 l0 = __float2bfloat16(x0 - __bfloat162float(h0));
    __nv_bfloat16 l1 = __float2bfloat16(x1 - __bfloat162float(h1));
    __nv_bfloat162 ph = __halves2bfloat162(h0, h1);
    __nv_bfloat162 pl = __halves2bfloat162(l0, l1);
    hi = *(uint32_t*)&ph;
    lo = *(uint32_t*)&pl;
}

// ---------------------------------------------------------------------------
// 3xbf16 GEMM (full fp32 fidelity): C[128,64] += A[128,K] @ B[K,64] (+bias)
// A row-major [m][k] (stride lda), B row-major [k][n] (stride ldb).
// 8 warps = 2(M) x 4(N); warp tile 64x16; m16n8k16 atoms; K staged in 32s.
// split a = ah + al, b = bh + bl; acc = ah*bh + ah*bl + al*bh.
// mode 0: out[m*512 + bn + n]               (dense, +bias)
// mode 1: out[((b*H + bn/64)*S + s)*64 + n] (per-head, +bias)
// mode 2: ctx[(b*S + s)*512 + h*64 + n]     (AV epilogue, h = blockIdx.z%PH)
// ---------------------------------------------------------------------------
__global__ __launch_bounds__(256) void mma_gemm_kernel(const float* __restrict__ Abase,
                                                       const float* __restrict__ Bbase,
                                                       const float* __restrict__ bias,
                                                       float* __restrict__ out,
                                                       int K, int lda, int ldb, int mode)
{
    const int STR = 40;  // bf16 elements per smem row (32 + 8 pad); 80B, 16B-aligned
    __shared__ __align__(16) __nv_bfloat16 Ah[128 * STR];
    __shared__ __align__(16) __nv_bfloat16 Al[128 * STR];
    __shared__ __align__(16) __nv_bfloat16 Bh[64 * STR];
    __shared__ __align__(16) __nv_bfloat16 Bl[64 * STR];

    const int tid  = threadIdx.x;
    const int wid  = tid >> 5;
    const int lane = tid & 31;
    const int wm   = wid >> 2;     // 0..1
    const int wn   = wid & 3;      // 0..3

    const int bm = blockIdx.y * 128;
    const int bn = (mode == 2) ? 0 : blockIdx.x * 64;
    const int zz = blockIdx.z;

    const float* A = Abase + (mode == 2 ? (size_t)zz * PS * PS : 0);
    const float* B = Bbase + (mode == 2 ? (size_t)zz * PS * PDH : 0);

    const uint32_t ah_b = smem_u32(Ah), al_b = smem_u32(Al);
    const uint32_t bh_b = smem_u32(Bh), bl_b = smem_u32(Bl);

    float acc[4][2][4] = {};

    for (int kt = 0; kt < K; kt += 32) {
        // A tile: 128 x 32 fp32 -> hi/lo bf16 (pair packs)
        #pragma unroll
        for (int idx = tid; idx < 2048; idx += 256) {
            int r = idx >> 4, pc = idx & 15;
            float2 a2 = *(const float2*)&A[(size_t)(bm + r) * lda + kt + 2 * pc];
            uint32_t hi, lo;
            split2(a2.x, a2.y, hi, lo);
            *(uint32_t*)&Ah[r * STR + 2 * pc] = hi;
            *(uint32_t*)&Al[r * STR + 2 * pc] = lo;
        }
        // B tile: 32 x 64 [k][n] -> transpose to Bs[n][k]
        #pragma unroll
        for (int idx = tid; idx < 2048; idx += 256) {
            int k = idx >> 6, n = idx & 63;
            float v = B[(size_t)(kt + k) * ldb + bn + n];
            __nv_bfloat16 h = __float2bfloat16(v);
            __nv_bfloat16 l = __float2bfloat16(v - __bfloat162float(h));
            Bh[n * STR + k] = h;
            Bl[n * STR + k] = l;
        }
        __syncthreads();

        #pragma unroll
        for (int ks = 0; ks < 2; ks++) {
            const int k0 = ks * 16;
            uint32_t afh[4][4], afl[4][4];
            #pragma unroll
            for (int mt = 0; mt < 4; mt++) {
                int row = wm * 64 + mt * 16 + (lane & 15);
                int col = k0 + ((lane >> 4) << 3);
                uint32_t off = (uint32_t)(row * STR + col) * 2;
                LDSMX4(afh[mt], ah_b + off);
                LDSMX4(afl[mt], al_b + off);
            }
            uint32_t bfh[2][2], bfl[2][2];
            #pragma unroll
            for (int nt = 0; nt < 2; nt++) {
                int l16 = lane & 15;
                int row = wn * 16 + nt * 8 + (l16 & 7);
                int col = k0 + ((l16 >> 3) << 3);
                uint32_t off = (uint32_t)(row * STR + col) * 2;
                LDSMX2(bfh[nt], bh_b + off);
                LDSMX2(bfl[nt], bl_b + off);
            }
            #pragma unroll
            for (int mt = 0; mt < 4; mt++)
                #pragma unroll
                for (int nt = 0; nt < 2; nt++) {
                    MMA16816(acc[mt][nt], afh[mt], bfh[nt]);
                    MMA16816(acc[mt][nt], afh[mt], bfl[nt]);
                    MMA16816(acc[mt][nt], afl[mt], bfh[nt]);
                }
        }
        __syncthreads();
    }

    // Epilogue. Frag: g = lane>>2 (row), tg = lane&3 (col pair);
    // d0=(g,2tg) d1=(g,2tg+1) d2=(g+8,2tg) d3=(g+8,2tg+1).
    const int g  = lane >> 2;
    const int tg = lane & 3;

    float bb[2][2] = {};
    if (bias) {
        #pragma unroll
        for (int nt = 0; nt < 2; nt++)
            *(float2*)&bb[nt][0] = *(const float2*)&bias[bn + wn * 16 + nt * 8 + tg * 2];
    }

    #pragma unroll
    for (int mt = 0; mt < 4; mt++) {
        int m0 = bm + wm * 64 + mt * 16 + g;   // global row (and m0+8)
        #pragma unroll
        for (int nt = 0; nt < 2; nt++) {
            int nl = wn * 16 + nt * 8 + tg * 2;      // local col 0..63
            float2 v0 = make_float2(acc[mt][nt][0] + bb[nt][0],
                                    acc[mt][nt][1] + bb[nt][1]);
            float2 v1 = make_float2(acc[mt][nt][2] + bb[nt][0],
                                    acc[mt][nt][3] + bb[nt][1]);
            if (mode == 0) {
                *(float2*)&out[(size_t)m0 * PDM + bn + nl]       = v0;
                *(float2*)&out[(size_t)(m0 + 8) * PDM + bn + nl] = v1;
            } else if (mode == 1) {
                int b0 = m0 / PS, s0 = m0 % PS;
                int b1 = (m0 + 8) / PS, s1 = (m0 + 8) % PS;
                int h_ = bn / PDH;
                *(float2*)&out[(((size_t)(b0 * PH + h_) * PS + s0)) * PDH + nl] = v0;
                *(float2*)&out[(((size_t)(b1 * PH + h_) * PS + s1)) * PDH + nl] = v1;
            } else {
                int b_ = zz / PH, h_ = zz % PH;
                *(float2*)&out[((size_t)b_ * PS + m0) * PDM + h_ * PDH + nl]       = v0;
                *(float2*)&out[((size_t)b_ * PS + m0 + 8) * PDM + h_ * PDH + nl]   = v1;
            }
        }
    }
}

// ---------------------------------------------------------------------------
// Score GEMM (single bf16 HMMA): per (b,h)
//   out[bh][i][j] = SCALE * sum_d (Q[i,d] + hb[h,d]) * M[j,d]
// Plain coalesced store (rel-shift handled at softmax read). 128x128 / block.
// ---------------------------------------------------------------------------
__global__ __launch_bounds__(256) void score_mma_kernel(const float* __restrict__ Q,
                                                        const float* __restrict__ M,
                                                        const float* __restrict__ hb,
                                                        float* __restrict__ out)
{
    const int LDS = 72;
    __shared__ __align__(16) __nv_bfloat16 As[128 * LDS];
    __shared__ __align__(16) __nv_bfloat16 Bs[128 * LDS];

    const int tid  = threadIdx.x;
    const int wid  = tid >> 5;
    const int lane = tid & 31;
    const int bh = blockIdx.z;
    const int h  = bh & (PH - 1);
    const int i0 = blockIdx.y * 128;
    const int j0 = blockIdx.x * 128;

    const float* Qb = Q + (size_t)bh * PS * PDH;
    const float* Mb = M + (size_t)bh * PS * PDH;
    #pragma unroll
    for (int idx = tid; idx < 128 * 32; idx += 256) {
        int r = idx >> 5, pc = idx & 31;
        float2 q2 = *(const float2*)&Qb[(size_t)(i0 + r) * PDH + 2 * pc];
        float2 b2 = *(const float2*)&hb[h * PDH + 2 * pc];
        __nv_bfloat162 pk = __floats2bfloat162_rn((q2.x + b2.x) * SCALE,
                                                  (q2.y + b2.y) * SCALE);
        *(uint32_t*)&As[r * LDS + pc * 2] = *(uint32_t*)&pk;
    }
    #pragma unroll
    for (int idx = tid; idx < 128 * 32; idx += 256) {
        int r = idx >> 5, pc = idx & 31;
        float2 m2 = *(const float2*)&Mb[(size_t)(j0 + r) * PDH + 2 * pc];
        __nv_bfloat162 pk = __floats2bfloat162_rn(m2.x, m2.y);
        *(uint32_t*)&Bs[r * LDS + pc * 2] = *(uint32_t*)&pk;
    }
    __syncthreads();

    const int wm = wid >> 2;
    const int wn = wid & 3;
    const uint32_t a_base = smem_u32(As);
    const uint32_t b_base = smem_u32(Bs);

    float acc[4][4][4] = {};

    #pragma unroll
    for (int ks = 0; ks < 4; ks++) {
        const int k0 = ks * 16;
        uint32_t a[4][4];
        #pragma unroll
        for (int mt = 0; mt < 4; mt++) {
            int row = wm * 64 + mt * 16 + (lane & 15);
            int col = k0 + ((lane >> 4) << 3);
            LDSMX4(a[mt], a_base + (uint32_t)(row * LDS + col) * 2);
        }
        uint32_t b[4][2];
        #pragma unroll
        for (int nt = 0; nt < 4; nt++) {
            int l16 = lane & 15;
            int row = wn * 32 + nt * 8 + (l16 & 7);
            int col = k0 + ((l16 >> 3) << 3);
            LDSMX2(b[nt], b_base + (uint32_t)(row * LDS + col) * 2);
        }
        #pragma unroll
        for (int mt = 0; mt < 4; mt++)
            #pragma unroll
            for (int nt = 0; nt < 4; nt++)
                MMA16816(acc[mt][nt], a[mt], b[nt]);
    }

    const int g  = lane >> 2;
    const int tg = lane & 3;
    float* sb = out + (size_t)bh * PS * PS;

    #pragma unroll
    for (int mt = 0; mt < 4; mt++) {
        int gi = i0 + wm * 64 + mt * 16 + g;
        #pragma unroll
        for (int nt = 0; nt < 4; nt++) {
            int gj = j0 + wn * 32 + nt * 8 + tg * 2;
            *(float2*)&sb[(size_t)gi * PS + gj] =
                make_float2(acc[mt][nt][0], acc[mt][nt][1]);
            *(float2*)&sb[(size_t)(gi + 8) * PS + gj] =
                make_float2(acc[mt][nt][2], acc[mt][nt][3]);
        }
    }
}

// ---------------------------------------------------------------------------
// Fused rel-shift + add + softmax. One block (256 threads) per row r:
//   x[j] = content[r][j] + shiftedpos[r][j]   (both already scaled)
//   shiftedpos[r][j] = pos[r][j+S-1-r]  (j<=r) | 0 (j==r+1) | pos[r+1][j-r-2]
// Reads are two contiguous segments of pos -> fully coalesced.
// Writes attn (in place over content).
// ---------------------------------------------------------------------------
__global__ __launch_bounds__(256) void softmax_kernel(float* __restrict__ score,
                                                      const float* __restrict__ pos,
                                                      const unsigned char* __restrict__ mask)
{
    const size_t row = blockIdx.x;           // bh*S + r
    const int bh = (int)(row / PS);
    const int r  = (int)(row % PS);
    const int b_ = bh / PH;
    float* cp = score + row * (size_t)PS;
    const float* pr  = pos + row * (size_t)PS;       // pos row r
    const float* pr1 = pr + PS;                      // pos row r+1 (guarded)
    const unsigned char* mrow = mask + (size_t)b_ * PS;

    const int tid  = threadIdx.x;
    const int lane = tid & 31;
    const int wid  = tid >> 5;

    __shared__ float s1[8];
    __shared__ float s2[8];

    float x[8];
    unsigned long long mk = *(const unsigned long long*)&mrow[8 * tid];

    float mx = -INFINITY;
    #pragma unroll
    for (int t = 0; t < 8; t++) {
        int j = 8 * tid + t;
        float pv;
        if (j <= r)           pv = pr[j + (PS - 1) - r];
        else if (j == r + 1)  pv = 0.0f;
        else                  pv = pr1[j - r - 2];
        float v = cp[j] + pv;
        x[t] = ((mk >> (8 * t)) & 0xffULL) ? -1e9f : v;
        mx = fmaxf(mx, x[t]);
    }
    #pragma unroll
    for (int o = 16; o > 0; o >>= 1)
        mx = fmaxf(mx, __shfl_xor_sync(0xffffffffu, mx, o));
    if (lane == 0) s1[wid] = mx;
    __syncthreads();
    mx = s1[0];
    #pragma unroll
    for (int w = 1; w < 8; w++) mx = fmaxf(mx, s1[w]);

    float sum = 0.0f;
    #pragma unroll
    for (int t = 0; t < 8; t++) {
        x[t] = expf(x[t] - mx);
        sum += x[t];
    }
    #pragma unroll
    for (int o = 16; o > 0; o >>= 1)
        sum += __shfl_xor_sync(0xffffffffu, sum, o);
    if (lane == 0) s2[wid] = sum;
    __syncthreads();
    sum = s2[0];
    #pragma unroll
    for (int w = 1; w < 8; w++) sum += s2[w];
    float inv = 1.0f / sum;

    float4 v0 = make_float4(x[0] * inv, x[1] * inv, x[2] * inv, x[3] * inv);
    float4 v1 = make_float4(x[4] * inv, x[5] * inv, x[6] * inv, x[7] * inv);
    *(float4*)&cp[8 * tid]     = v0;
    *(float4*)&cp[8 * tid + 4] = v1;
}

// ---------------------------------------------------------------------------
extern "C" void kernel_launch(void* const* d_in, const int* in_sizes, int n_in,
                              void* d_out, int out_size)
{
    const float* query = (const float*)d_in[0];
    const float* key   = (const float*)d_in[1];
    const float* value = (const float*)d_in[2];
    const float* pos   = (const float*)d_in[3];
    const unsigned char* mask = (const unsigned char*)d_in[4];
    const float* Wq = (const float*)d_in[5];
    const float* bq = (const float*)d_in[6];
    const float* Wk = (const float*)d_in[7];
    const float* bk = (const float*)d_in[8];
    const float* Wv = (const float*)d_in[9];
    const float* bv = (const float*)d_in[10];
    const float* Wp = (const float*)d_in[11];
    const float* Wo = (const float*)d_in[12];
    const float* bo = (const float*)d_in[13];
    const float* ub = (const float*)d_in[14];
    const float* vb = (const float*)d_in[15];

    float *q, *k, *v, *p, *score, *posb, *ctx;
    cudaGetSymbolAddress((void**)&q, g_q);
    cudaGetSymbolAddress((void**)&k, g_k);
    cudaGetSymbolAddress((void**)&v, g_v);
    cudaGetSymbolAddress((void**)&p, g_p);
    cudaGetSymbolAddress((void**)&score, g_score);
    cudaGetSymbolAddress((void**)&posb, g_pos);
    cudaGetSymbolAddress((void**)&ctx, g_ctx);

    dim3 tb(256);

    // 1) projections (3xbf16 HMMA) -> [b,h,s,d]
    dim3 gproj(PDM / 64, (PB * PS) / 128, 1);
    mma_gemm_kernel<<<gproj, tb>>>(query, Wq, bq, q, PDM, PDM, PDM, 1);
    mma_gemm_kernel<<<gproj, tb>>>(key,   Wk, bk, k, PDM, PDM, PDM, 1);
    mma_gemm_kernel<<<gproj, tb>>>(value, Wv, bv, v, PDM, PDM, PDM, 1);
    mma_gemm_kernel<<<gproj, tb>>>(pos,   Wp, nullptr, p, PDM, PDM, PDM, 1);

    // 2) content + (unshifted) pos scores, plain stores, scale folded in
    dim3 gscore(PS / 128, PS / 128, NBH);
    score_mma_kernel<<<gscore, tb>>>(q, k, ub, score);
    score_mma_kernel<<<gscore, tb>>>(q, p, vb, posb);

    // 3) fused rel-shift + add + softmax -> attn (in place over score)
    softmax_kernel<<<NBH * PS, tb>>>(score, posb, mask);

    // 4) attn @ V (3xbf16 HMMA) -> ctx [b,s,h*d]
    mma_gemm_kernel<<<dim3(1, PS / 128, NBH), tb>>>(score, v, nullptr, ctx,
                                                    PS, PS, PDH, 2);

    // 5) output projection (3xbf16 HMMA) -> d_out [b,s,512]
    mma_gemm_kernel<<<gproj, tb>>>(ctx, Wo, bo, (float*)d_out, PDM, PDM, PDM, 0);
}